// round 3
// baseline (speedup 1.0000x reference)
#include <cuda_runtime.h>

// LatentODE2 R3: E=4 elems/warp, f32x2 packed over OUTPUT pairs (j, j+32).
// - Accumulators are u64 pairs (out_j, out_j+32) per element.
// - Weights pre-packed in SMEM as u64 pairs -> FFMA2 b-operand loads directly.
// - State (x,h) stored DUPLICATED (v,v) in SMEM -> FFMA2 a-operand loads directly.
// - No pk2/mov in inner loops; all addressing via constant offsets.
// - Persistent grid 888 (=148*6) CTAs x 64 thr; CTAs < 136 take a 2nd group.

#define T_STEPS 100
#define D_IN    16
#define H_DIM   32
#define HD_DIM  50
#define EULER   10
#define STEP_F  0.1f
#define DTS_F   (1.0f / 24.0f)

#define E        4          // elements per warp
#define NW       2          // warps per CTA
#define GRID     888        // 148 * 6
#define NGROUPS  1024       // 8192 / (NW*E)

typedef unsigned long long u64;

__device__ __forceinline__ u64 pk2(float lo, float hi) {
    u64 r; asm("mov.b64 %0, {%1, %2};" : "=l"(r) : "f"(lo), "f"(hi)); return r;
}
__device__ __forceinline__ void up2(u64 v, float& a, float& b) {
    asm("mov.b64 {%0, %1}, %2;" : "=f"(a), "=f"(b) : "l"(v));
}
__device__ __forceinline__ void fma2(u64& d, u64 a, u64 b) {
    asm("fma.rn.f32x2 %0, %1, %2, %0;" : "+l"(d) : "l"(a), "l"(b));
}
__device__ __forceinline__ u64 add2(u64 a, u64 b) {
    u64 r; asm("add.rn.f32x2 %0, %1, %2;" : "=l"(r) : "l"(a), "l"(b)); return r;
}

__device__ __forceinline__ float my_tanh(float v) {
    v = fminf(fmaxf(v, -15.0f), 15.0f);
    float e = __expf(2.0f * v);
    return __fdividef(e - 1.0f, e + 1.0f);
}
__device__ __forceinline__ u64 tanh2(u64 v) {
    float a, b; up2(v, a, b);
    return pk2(my_tanh(a), my_tanh(b));
}

__global__ void __launch_bounds__(NW * 32, 6)
latentode2_kernel(const float* __restrict__ dt,
                  const float* __restrict__ x,
                  const float* __restrict__ W1, const float* __restrict__ b1,
                  const float* __restrict__ W2, const float* __restrict__ b2,
                  const float* __restrict__ W3, const float* __restrict__ b3,
                  const float* __restrict__ W4, const float* __restrict__ b4,
                  float* __restrict__ out)
{
    // Pre-packed weights (pairs over outputs j / j+32):
    //   sW1x[k*32+j]   = pk2(W1[j][k],    W1[j+32][k])         k<16  (x part)
    //   sW13[k*32+j].x = pk2(W1[j][16+k], W1[j+32][16+k])      k<32  (h part)
    //   sW13[k*32+j].y = pk2(W3[j][k],    W3[j+32][k])
    //   sW2p[j*32+k]   = pk2(W2[k][j],    W2[k][j+32])         j<32
    __shared__ u64        sW1x[16 * 32];
    __shared__ ulonglong2 sW13[32 * 32];
    __shared__ u64        sW2p[32 * 32];
    // State, duplicated per element: sId rows 0..15 = x, 16..47 = h.
    __shared__ u64 sId[NW][48][E];
    __shared__ u64 sZp[NW][32][E];   // z pairs (z[j], z[j+32]) per element

    const int tid = threadIdx.x;

    for (int idx = tid; idx < 16 * 32; idx += NW * 32) {
        int k = idx >> 5, j = idx & 31;
        float hi = (j + 32 < HD_DIM) ? W1[(j + 32) * 48 + k] : 0.0f;
        sW1x[idx] = pk2(W1[j * 48 + k], hi);
    }
    for (int idx = tid; idx < 32 * 32; idx += NW * 32) {
        int k = idx >> 5, j = idx & 31;
        float hi = (j + 32 < HD_DIM) ? W1[(j + 32) * 48 + 16 + k] : 0.0f;
        ulonglong2 wu;
        wu.x = pk2(W1[j * 48 + 16 + k], hi);
        wu.y = pk2(W3[j * 32 + k], W3[(j + 32) * 32 + k]);
        sW13[idx] = wu;
    }
    for (int idx = tid; idx < 32 * 32; idx += NW * 32) {
        int j = idx >> 5, k = idx & 31;
        float hi = (j + 32 < HD_DIM) ? W2[k * 50 + (j + 32)] : 0.0f;
        sW2p[idx] = pk2(W2[k * 50 + j], hi);
    }
    __syncthreads();

    const int warp = tid >> 5;
    const int lane = tid & 31;

    // Per-lane packed constants.
    const float b1lo = b1[lane];
    const float b1hi = (lane + 32 < HD_DIM) ? b1[lane + 32] : 0.0f;
    const u64 PB1 = pk2(b1lo, b1hi);
    const u64 PB3 = pk2(b3[lane], b3[lane + 32]);
    const u64 PW4 = pk2(W4[lane], W4[lane + 32]);
    const float b2s = b2[lane];
    const u64 PB2 = pk2(b2s, 0.0f);
    const float b4v = b4[0];

    u64 (*Id)[E] = sId[warp];
    u64 (*Zp)[E] = sZp[warp];

    const float2* dt2 = (const float2*)dt;

    for (int grp = blockIdx.x; grp < NGROUPS; grp += GRID) {
        const int e0 = grp * (NW * E) + warp * E;

        // h = 0 (own row in regs + dup'd smem rows)
        float hreg[E] = {0.0f, 0.0f, 0.0f, 0.0f};
#pragma unroll
        for (int e = 0; e < E; e++) Id[16 + lane][e] = 0ull;
        __syncwarp();

#pragma unroll 1
        for (int t = 0; t < T_STEPS; t++) {
            // Stage x (dup'd) for this time step: lanes 0..15 handle feature=lane.
            if (lane < D_IN) {
#pragma unroll
                for (int e = 0; e < E; e++) {
                    float xv = x[((e0 + e) * T_STEPS + t) * D_IN + lane];
                    Id[lane][e] = pk2(xv, xv);
                }
            }
            // cs_e = STEP * (dt1-dt0) * DT_SCALER (all lanes, broadcast LDG).
            float cs[E];
#pragma unroll
            for (int e = 0; e < E; e++) {
                float2 d = dt2[(e0 + e) * T_STEPS + t];
                cs[e] = STEP_F * ((d.y - d.x) * DTS_F);
            }
            __syncwarp();

            // y init = x[:,0]
            float y[E];
#pragma unroll
            for (int e = 0; e < E; e++) {
                float a, b; up2(Id[0][e], a, b); (void)b;
                y[e] = a;
            }

#pragma unroll 1
            for (int s = 0; s < EULER; s++) {
                u64 z0 = PB1, z1 = PB1, z2 = PB1, z3 = PB1;
                u64 g0 = PB3, g1 = PB3, g2 = PB3, g3 = PB3;

                // x part of z1
#pragma unroll
                for (int k = 0; k < D_IN; k++) {
                    u64 w = sW1x[k * 32 + lane];
                    ulonglong2 vA = *(const ulonglong2*)&Id[k][0];
                    ulonglong2 vB = *(const ulonglong2*)&Id[k][2];
                    fma2(z0, vA.x, w); fma2(z1, vA.y, w);
                    fma2(z2, vB.x, w); fma2(z3, vB.y, w);
                }
                // h part of z1 fused with g = h @ W3^T
#pragma unroll
                for (int k = 0; k < H_DIM; k++) {
                    ulonglong2 wu = sW13[k * 32 + lane];
                    ulonglong2 vA = *(const ulonglong2*)&Id[16 + k][0];
                    ulonglong2 vB = *(const ulonglong2*)&Id[16 + k][2];
                    fma2(z0, vA.x, wu.x); fma2(z1, vA.y, wu.x);
                    fma2(z2, vB.x, wu.x); fma2(z3, vB.y, wu.x);
                    fma2(g0, vA.x, wu.y); fma2(g1, vA.y, wu.y);
                    fma2(g2, vB.x, wu.y); fma2(g3, vB.y, wu.y);
                }

                // z = tanh(z1-pre), publish pairs.
                {
                    ulonglong2 zA, zB;
                    zA.x = tanh2(z0); zA.y = tanh2(z1);
                    zB.x = tanh2(z2); zB.y = tanh2(z3);
                    *(ulonglong2*)&Zp[lane][0] = zA;
                    *(ulonglong2*)&Zp[lane][2] = zB;
                }

                // dy partials: tanh(g) * W4 pair, butterfly-reduce packed.
                u64 p0 = 0ull, p1 = 0ull, p2 = 0ull, p3 = 0ull;
                fma2(p0, tanh2(g0), PW4);
                fma2(p1, tanh2(g1), PW4);
                fma2(p2, tanh2(g2), PW4);
                fma2(p3, tanh2(g3), PW4);
#pragma unroll
                for (int off = 16; off > 0; off >>= 1) {
                    p0 = add2(p0, __shfl_xor_sync(0xffffffffu, p0, off));
                    p1 = add2(p1, __shfl_xor_sync(0xffffffffu, p1, off));
                    p2 = add2(p2, __shfl_xor_sync(0xffffffffu, p2, off));
                    p3 = add2(p3, __shfl_xor_sync(0xffffffffu, p3, off));
                }
                __syncwarp();   // z visible; all h reads of this step done

                // dh_pre (pair-split over j / j+32), one output k=lane.
                u64 d0 = PB2, d1 = PB2, d2 = PB2, d3 = PB2;
#pragma unroll
                for (int j = 0; j < H_DIM; j++) {
                    u64 w = sW2p[j * 32 + lane];
                    ulonglong2 zA = *(const ulonglong2*)&Zp[j][0];
                    ulonglong2 zB = *(const ulonglong2*)&Zp[j][2];
                    fma2(d0, zA.x, w); fma2(d1, zA.y, w);
                    fma2(d2, zB.x, w); fma2(d3, zB.y, w);
                }

                // Euler updates.
                u64 dd[E] = {d0, d1, d2, d3};
                u64 pp[E] = {p0, p1, p2, p3};
#pragma unroll
                for (int e = 0; e < E; e++) {
                    float A, B; up2(dd[e], A, B);
                    hreg[e] = fmaf(cs[e], my_tanh(A + B), hreg[e]);
                    float pA, pB; up2(pp[e], pA, pB);
                    y[e] = fmaf(cs[e], pA + pB + b4v, y[e]);
                }
                // Publish new h (dup'd).
#pragma unroll
                for (int e = 0; e < E; e++)
                    Id[16 + lane][e] = pk2(hreg[e], hreg[e]);
                __syncwarp();
            }

            if (lane < E)
                out[(e0 + lane) * T_STEPS + t] = y[lane];
        }
    }
}

extern "C" void kernel_launch(void* const* d_in, const int* in_sizes, int n_in,
                              void* d_out, int out_size) {
    (void)in_sizes; (void)n_in; (void)out_size;
    const float* dt = (const float*)d_in[0];
    const float* x  = (const float*)d_in[1];
    const float* W1 = (const float*)d_in[2];
    const float* b1 = (const float*)d_in[3];
    const float* W2 = (const float*)d_in[4];
    const float* b2 = (const float*)d_in[5];
    const float* W3 = (const float*)d_in[6];
    const float* b3 = (const float*)d_in[7];
    const float* W4 = (const float*)d_in[8];
    const float* b4 = (const float*)d_in[9];
    float* out = (float*)d_out;

    latentode2_kernel<<<GRID, NW * 32>>>(
        dt, x, W1, b1, W2, b2, W3, b3, W4, b4, out);
}

// round 5
// speedup vs baseline: 1.7895x; 1.7895x over previous
#include <cuda_runtime.h>

// LatentODE2 R4: R1 skeleton (E=4 elems/warp, lane = outputs {j, j+32}) with:
//  - x-contribution to z1 hoisted out of the Euler loop (x const across 10 steps)
//  - element-pair f32x2: state rows stored as ulonglong2 (two f32x2 operands
//    direct from one broadcast LDS.128); weight dup = 1 ALU MOV per weight
//  - W2 cached in registers (50 scalars/lane), dh-loop fully unrolled
// Crossbar model (calibrated on R1/R3): bcast LDS.128=2cyc, LDS.64-dist=2, LDS.32=1.

#define T_STEPS 100
#define D_IN    16
#define H_DIM   32
#define HD_DIM  50
#define EULER   10
#define STEP_F  0.1f
#define DTS_F   (1.0f / 24.0f)

#define NW      2
#define E       4
#define GRID    1024        // 8192 / (NW*E)

typedef unsigned long long u64;

__device__ __forceinline__ u64 pk2(float lo, float hi) {
    u64 r; asm("mov.b64 %0, {%1, %2};" : "=l"(r) : "f"(lo), "f"(hi)); return r;
}
__device__ __forceinline__ void up2(u64 v, float& a, float& b) {
    asm("mov.b64 {%0, %1}, %2;" : "=f"(a), "=f"(b) : "l"(v));
}
__device__ __forceinline__ void fma2(u64& d, u64 a, u64 b) {
    asm("fma.rn.f32x2 %0, %1, %2, %0;" : "+l"(d) : "l"(a), "l"(b));
}

__device__ __forceinline__ float my_tanh(float v) {
    v = fminf(fmaxf(v, -15.0f), 15.0f);
    float e = __expf(2.0f * v);
    return __fdividef(e - 1.0f, e + 1.0f);
}

__global__ void __launch_bounds__(NW * 32, 7)
latentode2_kernel(const float* __restrict__ dt,
                  const float* __restrict__ x,
                  const float* __restrict__ W1, const float* __restrict__ b1,
                  const float* __restrict__ W2, const float* __restrict__ b2,
                  const float* __restrict__ W3, const float* __restrict__ b3,
                  const float* __restrict__ W4, const float* __restrict__ b4,
                  float* __restrict__ out)
{
    // sW1x[k*32+j] = (W1[j][k], W1[j+32][k])                      k<16 (x part)
    // sW13[k*32+j] = (W1[j][16+k], W1[j+32][16+k], W3[j][k], W3[j+32][k])  k<32
    __shared__ float2 sW1x[16 * 32];
    __shared__ float4 sW13[32 * 32];
    // State rows: .x = (e0,e1) f32x2, .y = (e2,e3) f32x2.
    __shared__ ulonglong2 sX[NW][D_IN];
    __shared__ ulonglong2 sH[NW][H_DIM];
    __shared__ ulonglong2 sZ[NW][HD_DIM];

    const int tid = threadIdx.x;

    for (int idx = tid; idx < 16 * 32; idx += NW * 32) {
        int k = idx >> 5, j = idx & 31;
        float hi = (j + 32 < HD_DIM) ? W1[(j + 32) * 48 + k] : 0.0f;
        sW1x[idx] = make_float2(W1[j * 48 + k], hi);
    }
    for (int idx = tid; idx < 32 * 32; idx += NW * 32) {
        int k = idx >> 5, j = idx & 31;
        float w1hi = (j + 32 < HD_DIM) ? W1[(j + 32) * 48 + 16 + k] : 0.0f;
        sW13[idx] = make_float4(W1[j * 48 + 16 + k], w1hi,
                                W3[j * 32 + k], W3[(j + 32) * 32 + k]);
    }
    __syncthreads();

    const int warp = tid >> 5;
    const int lane = tid & 31;
    const int e0   = (blockIdx.x * NW + warp) * E;

    // Register-cached W2 row (lane = output k of dh): W2[lane][j], j<50.
    float w2r[HD_DIM];
#pragma unroll
    for (int j = 0; j < HD_DIM; j++) w2r[j] = W2[lane * HD_DIM + j];

    const float b1lo = b1[lane];
    const float b1hi = (lane + 32 < HD_DIM) ? b1[lane + 32] : 0.0f;
    const float b3lo = b3[lane];
    const float b3hi = b3[lane + 32];
    const u64 PB3lo = pk2(b3lo, b3lo);
    const u64 PB3hi = pk2(b3hi, b3hi);
    const float b2s = b2[lane];
    const u64 PB2 = pk2(b2s, b2s);
    const float b4v = b4[0];
    const float w4a = W4[lane];
    const float w4b = W4[lane + 32];

    ulonglong2* Xs = sX[warp];
    ulonglong2* Hs = sH[warp];
    ulonglong2* Zs = sZ[warp];

    // h = 0
    float h0 = 0.0f, h1 = 0.0f, h2 = 0.0f, h3 = 0.0f;
    Hs[lane] = make_ulonglong2(0ull, 0ull);
    __syncwarp();

    const float2* dt2 = (const float2*)dt;

#pragma unroll 1
    for (int t = 0; t < T_STEPS; t++) {
        // Stage x rows for this t (lanes 0..15).
        if (lane < D_IN) {
            float x0 = x[((e0 + 0) * T_STEPS + t) * D_IN + lane];
            float x1 = x[((e0 + 1) * T_STEPS + t) * D_IN + lane];
            float x2 = x[((e0 + 2) * T_STEPS + t) * D_IN + lane];
            float x3 = x[((e0 + 3) * T_STEPS + t) * D_IN + lane];
            Xs[lane] = make_ulonglong2(pk2(x0, x1), pk2(x2, x3));
        }
        float cs0, cs1, cs2, cs3;
        {
            float2 d0 = dt2[(e0 + 0) * T_STEPS + t];
            float2 d1 = dt2[(e0 + 1) * T_STEPS + t];
            float2 d2 = dt2[(e0 + 2) * T_STEPS + t];
            float2 d3 = dt2[(e0 + 3) * T_STEPS + t];
            cs0 = STEP_F * ((d0.y - d0.x) * DTS_F);
            cs1 = STEP_F * ((d1.y - d1.x) * DTS_F);
            cs2 = STEP_F * ((d2.y - d2.x) * DTS_F);
            cs3 = STEP_F * ((d3.y - d3.x) * DTS_F);
        }
        __syncwarp();

        // z1x = b1 + x @ W1x^T  (once per t, reused for all 10 Euler steps)
        u64 zxj01 = pk2(b1lo, b1lo), zxj23 = zxj01;
        u64 zxk01 = pk2(b1hi, b1hi), zxk23 = zxk01;
#pragma unroll
        for (int k = 0; k < D_IN; k++) {
            ulonglong2 v = Xs[k];
            float2 w = sW1x[k * 32 + lane];
            u64 wl = pk2(w.x, w.x), wh = pk2(w.y, w.y);
            fma2(zxj01, v.x, wl); fma2(zxj23, v.y, wl);
            fma2(zxk01, v.x, wh); fma2(zxk23, v.y, wh);
        }

        // y init = x[:, 0]
        float y0, y1, y2, y3;
        { ulonglong2 v = Xs[0]; up2(v.x, y0, y1); up2(v.y, y2, y3); }

#pragma unroll 1
        for (int s = 0; s < EULER; s++) {
            u64 zj01 = zxj01, zj23 = zxj23, zk01 = zxk01, zk23 = zxk23;
            u64 gj01 = PB3lo, gj23 = PB3lo, gk01 = PB3hi, gk23 = PB3hi;

            // Fused: z1 += h @ W1h^T ; g = b3 + h @ W3^T
#pragma unroll
            for (int k = 0; k < H_DIM; k++) {
                ulonglong2 v = Hs[k];
                float4 w = sW13[k * 32 + lane];
                u64 w1l = pk2(w.x, w.x), w1h = pk2(w.y, w.y);
                u64 w3l = pk2(w.z, w.z), w3h = pk2(w.w, w.w);
                fma2(zj01, v.x, w1l); fma2(zj23, v.y, w1l);
                fma2(zk01, v.x, w1h); fma2(zk23, v.y, w1h);
                fma2(gj01, v.x, w3l); fma2(gj23, v.y, w3l);
                fma2(gk01, v.x, w3h); fma2(gk23, v.y, w3h);
            }

            // z = tanh(z1), publish rows lane and lane+32.
            {
                float a, b, c, d;
                up2(zj01, a, b); up2(zj23, c, d);
                Zs[lane] = make_ulonglong2(pk2(my_tanh(a), my_tanh(b)),
                                           pk2(my_tanh(c), my_tanh(d)));
                if (lane + 32 < HD_DIM) {
                    up2(zk01, a, b); up2(zk23, c, d);
                    Zs[lane + 32] = make_ulonglong2(pk2(my_tanh(a), my_tanh(b)),
                                                    pk2(my_tanh(c), my_tanh(d)));
                }
            }

            // dy partials: p_e = tanh(gj_e)*w4a + tanh(gk_e)*w4b, reduce over lanes.
            float p0, p1, p2, p3;
            {
                float a, b, c, d;
                up2(gj01, a, b); up2(gk01, c, d);
                p0 = fmaf(my_tanh(a), w4a, my_tanh(c) * w4b);
                p1 = fmaf(my_tanh(b), w4a, my_tanh(d) * w4b);
                up2(gj23, a, b); up2(gk23, c, d);
                p2 = fmaf(my_tanh(a), w4a, my_tanh(c) * w4b);
                p3 = fmaf(my_tanh(b), w4a, my_tanh(d) * w4b);
            }
#pragma unroll
            for (int off = 16; off > 0; off >>= 1) {
                p0 += __shfl_xor_sync(0xffffffffu, p0, off);
                p1 += __shfl_xor_sync(0xffffffffu, p1, off);
                p2 += __shfl_xor_sync(0xffffffffu, p2, off);
                p3 += __shfl_xor_sync(0xffffffffu, p3, off);
            }
            __syncwarp();   // z published; all h-loop reads of this step done

            // dh_pre = b2 + z @ W2^T (out k = lane), W2 row in registers.
            u64 d01 = PB2, d23 = PB2;
#pragma unroll
            for (int j = 0; j < HD_DIM; j++) {
                ulonglong2 zz = Zs[j];
                u64 wd = pk2(w2r[j], w2r[j]);
                fma2(d01, zz.x, wd);
                fma2(d23, zz.y, wd);
            }

            // Euler updates.
            {
                float a, b, c, d;
                up2(d01, a, b); up2(d23, c, d);
                h0 = fmaf(cs0, my_tanh(a), h0);
                h1 = fmaf(cs1, my_tanh(b), h1);
                h2 = fmaf(cs2, my_tanh(c), h2);
                h3 = fmaf(cs3, my_tanh(d), h3);
            }
            y0 = fmaf(cs0, p0 + b4v, y0);
            y1 = fmaf(cs1, p1 + b4v, y1);
            y2 = fmaf(cs2, p2 + b4v, y2);
            y3 = fmaf(cs3, p3 + b4v, y3);

            Hs[lane] = make_ulonglong2(pk2(h0, h1), pk2(h2, h3));
            __syncwarp();
        }

        if (lane < E) {
            float yv = (lane == 0) ? y0 : (lane == 1) ? y1 : (lane == 2) ? y2 : y3;
            out[(e0 + lane) * T_STEPS + t] = yv;
        }

        // Reset h for next group? No — h carries across t within same elements.
    }
}

extern "C" void kernel_launch(void* const* d_in, const int* in_sizes, int n_in,
                              void* d_out, int out_size) {
    (void)in_sizes; (void)n_in; (void)out_size;
    const float* dt = (const float*)d_in[0];
    const float* x  = (const float*)d_in[1];
    const float* W1 = (const float*)d_in[2];
    const float* b1 = (const float*)d_in[3];
    const float* W2 = (const float*)d_in[4];
    const float* b2 = (const float*)d_in[5];
    const float* W3 = (const float*)d_in[6];
    const float* b3 = (const float*)d_in[7];
    const float* W4 = (const float*)d_in[8];
    const float* b4 = (const float*)d_in[9];
    float* out = (float*)d_out;

    latentode2_kernel<<<GRID, NW * 32>>>(
        dt, x, W1, b1, W2, b2, W3, b3, W4, b4, out);
}

// round 6
// speedup vs baseline: 1.9283x; 1.0776x over previous
#include <cuda_runtime.h>

// LatentODE2 R6: R4 structure scaled to E=8 elems/warp (1 warp = 1 CTA).
// Lane j owns output pair (j, j+32). State rows are 8 floats = two ulonglong2
// halves (each = two f32x2 operands straight from broadcast LDS.128).
// Weight float4 LDS (4 cyc) now amortized over 32 FLOP-pairs instead of 16.
// W2 row cached in registers; x-contribution to z1 hoisted out of Euler loop.

#define T_STEPS 100
#define D_IN    16
#define H_DIM   32
#define HD_DIM  50
#define EULER   10
#define STEP_F  0.1f
#define DTS_F   (1.0f / 24.0f)

#define E       8
#define GRID    1024        // 8192 / 8, 32-thread CTAs

typedef unsigned long long u64;

__device__ __forceinline__ u64 pk2(float lo, float hi) {
    u64 r; asm("mov.b64 %0, {%1, %2};" : "=l"(r) : "f"(lo), "f"(hi)); return r;
}
__device__ __forceinline__ void up2(u64 v, float& a, float& b) {
    asm("mov.b64 {%0, %1}, %2;" : "=f"(a), "=f"(b) : "l"(v));
}
__device__ __forceinline__ void fma2(u64& d, u64 a, u64 b) {
    asm("fma.rn.f32x2 %0, %1, %2, %0;" : "+l"(d) : "l"(a), "l"(b));
}

__device__ __forceinline__ float my_tanh(float v) {
    v = fminf(fmaxf(v, -15.0f), 15.0f);
    float e = __expf(2.0f * v);
    return __fdividef(e - 1.0f, e + 1.0f);
}
__device__ __forceinline__ u64 tanh2(u64 v) {
    float a, b; up2(v, a, b);
    return pk2(my_tanh(a), my_tanh(b));
}

__global__ void __launch_bounds__(32, 7)
latentode2_kernel(const float* __restrict__ dt,
                  const float* __restrict__ x,
                  const float* __restrict__ W1, const float* __restrict__ b1,
                  const float* __restrict__ W2, const float* __restrict__ b2,
                  const float* __restrict__ W3, const float* __restrict__ b3,
                  const float* __restrict__ W4, const float* __restrict__ b4,
                  float* __restrict__ out)
{
    // sW1x[k*32+j] = (W1[j][k], W1[j+32][k])                      k<16 (x part)
    // sW13[k*32+j] = (W1[j][16+k], W1[j+32][16+k], W3[j][k], W3[j+32][k])  k<32
    __shared__ float2 sW1x[16 * 32];
    __shared__ float4 sW13[32 * 32];
    // State rows, split: A = elems 0..3 (two f32x2), B = elems 4..7.
    __shared__ ulonglong2 sXA[D_IN],  sXB[D_IN];
    __shared__ ulonglong2 sHA[H_DIM], sHB[H_DIM];
    __shared__ ulonglong2 sZA[HD_DIM], sZB[HD_DIM];

    const int lane = threadIdx.x;

    for (int idx = lane; idx < 16 * 32; idx += 32) {
        int k = idx >> 5, j = idx & 31;
        float hi = (j + 32 < HD_DIM) ? W1[(j + 32) * 48 + k] : 0.0f;
        sW1x[idx] = make_float2(W1[j * 48 + k], hi);
    }
    for (int idx = lane; idx < 32 * 32; idx += 32) {
        int k = idx >> 5, j = idx & 31;
        float w1hi = (j + 32 < HD_DIM) ? W1[(j + 32) * 48 + 16 + k] : 0.0f;
        sW13[idx] = make_float4(W1[j * 48 + 16 + k], w1hi,
                                W3[j * 32 + k], W3[(j + 32) * 32 + k]);
    }

    const int e0 = blockIdx.x * E;

    // W2 row in registers (lane = output k of dh).
    float w2r[HD_DIM];
#pragma unroll
    for (int j = 0; j < HD_DIM; j++) w2r[j] = W2[lane * HD_DIM + j];

    const float b1lo = b1[lane];
    const float b1hi = (lane + 32 < HD_DIM) ? b1[lane + 32] : 0.0f;
    const u64 PB3lo = pk2(b3[lane], b3[lane]);
    const u64 PB3hi = pk2(b3[lane + 32], b3[lane + 32]);
    const float b2s = b2[lane];
    const u64 PB2 = pk2(b2s, b2s);
    const float b4v = b4[0];
    const float w4a = W4[lane];
    const float w4b = W4[lane + 32];

    // h state (8 elems, own row) in registers + SMEM mirror.
    float h0 = 0, h1 = 0, h2 = 0, h3 = 0, h4 = 0, h5 = 0, h6 = 0, h7 = 0;
    sHA[lane] = make_ulonglong2(0ull, 0ull);
    sHB[lane] = make_ulonglong2(0ull, 0ull);
    __syncwarp();

    const float2* dt2 = (const float2*)dt;

#pragma unroll 1
    for (int t = 0; t < T_STEPS; t++) {
        // Stage x rows (lanes 0..15 handle feature = lane).
        if (lane < D_IN) {
            float xv[E];
#pragma unroll
            for (int e = 0; e < E; e++)
                xv[e] = x[((e0 + e) * T_STEPS + t) * D_IN + lane];
            sXA[lane] = make_ulonglong2(pk2(xv[0], xv[1]), pk2(xv[2], xv[3]));
            sXB[lane] = make_ulonglong2(pk2(xv[4], xv[5]), pk2(xv[6], xv[7]));
        }
        float cs[E];
#pragma unroll
        for (int e = 0; e < E; e++) {
            float2 d = dt2[(e0 + e) * T_STEPS + t];
            cs[e] = STEP_F * ((d.y - d.x) * DTS_F);
        }
        __syncwarp();

        // Hoisted: zx = b1 + x @ W1x^T (reused across all 10 Euler steps).
        u64 zxj01 = pk2(b1lo, b1lo), zxj23 = zxj01, zxj45 = zxj01, zxj67 = zxj01;
        u64 zxk01 = pk2(b1hi, b1hi), zxk23 = zxk01, zxk45 = zxk01, zxk67 = zxk01;
#pragma unroll
        for (int k = 0; k < D_IN; k++) {
            ulonglong2 vA = sXA[k], vB = sXB[k];
            float2 w = sW1x[k * 32 + lane];
            u64 wl = pk2(w.x, w.x), wh = pk2(w.y, w.y);
            fma2(zxj01, vA.x, wl); fma2(zxj23, vA.y, wl);
            fma2(zxj45, vB.x, wl); fma2(zxj67, vB.y, wl);
            fma2(zxk01, vA.x, wh); fma2(zxk23, vA.y, wh);
            fma2(zxk45, vB.x, wh); fma2(zxk67, vB.y, wh);
        }

        // y init = x[:, 0]
        float y0, y1, y2, y3, y4, y5, y6, y7;
        { ulonglong2 v = sXA[0]; up2(v.x, y0, y1); up2(v.y, y2, y3); }
        { ulonglong2 v = sXB[0]; up2(v.x, y4, y5); up2(v.y, y6, y7); }

#pragma unroll 1
        for (int s = 0; s < EULER; s++) {
            u64 zj01 = zxj01, zj23 = zxj23, zj45 = zxj45, zj67 = zxj67;
            u64 zk01 = zxk01, zk23 = zxk23, zk45 = zxk45, zk67 = zxk67;
            u64 gj01 = PB3lo, gj23 = PB3lo, gj45 = PB3lo, gj67 = PB3lo;
            u64 gk01 = PB3hi, gk23 = PB3hi, gk45 = PB3hi, gk67 = PB3hi;

            // Fused: z1 += h @ W1h^T ; g = b3 + h @ W3^T
#pragma unroll
            for (int k = 0; k < H_DIM; k++) {
                ulonglong2 vA = sHA[k], vB = sHB[k];
                float4 w = sW13[k * 32 + lane];
                u64 w1l = pk2(w.x, w.x), w1h = pk2(w.y, w.y);
                u64 w3l = pk2(w.z, w.z), w3h = pk2(w.w, w.w);
                fma2(zj01, vA.x, w1l); fma2(zj23, vA.y, w1l);
                fma2(zj45, vB.x, w1l); fma2(zj67, vB.y, w1l);
                fma2(zk01, vA.x, w1h); fma2(zk23, vA.y, w1h);
                fma2(zk45, vB.x, w1h); fma2(zk67, vB.y, w1h);
                fma2(gj01, vA.x, w3l); fma2(gj23, vA.y, w3l);
                fma2(gj45, vB.x, w3l); fma2(gj67, vB.y, w3l);
                fma2(gk01, vA.x, w3h); fma2(gk23, vA.y, w3h);
                fma2(gk45, vB.x, w3h); fma2(gk67, vB.y, w3h);
            }

            // z = tanh(z1-pre), publish rows lane and lane+32.
            sZA[lane] = make_ulonglong2(tanh2(zj01), tanh2(zj23));
            sZB[lane] = make_ulonglong2(tanh2(zj45), tanh2(zj67));
            if (lane + 32 < HD_DIM) {
                sZA[lane + 32] = make_ulonglong2(tanh2(zk01), tanh2(zk23));
                sZB[lane + 32] = make_ulonglong2(tanh2(zk45), tanh2(zk67));
            }

            // dy partials per element, butterfly-reduced over lanes.
            float p0, p1, p2, p3, p4, p5, p6, p7;
            {
                float a, b, c, d;
                up2(gj01, a, b); up2(gk01, c, d);
                p0 = fmaf(my_tanh(a), w4a, my_tanh(c) * w4b);
                p1 = fmaf(my_tanh(b), w4a, my_tanh(d) * w4b);
                up2(gj23, a, b); up2(gk23, c, d);
                p2 = fmaf(my_tanh(a), w4a, my_tanh(c) * w4b);
                p3 = fmaf(my_tanh(b), w4a, my_tanh(d) * w4b);
                up2(gj45, a, b); up2(gk45, c, d);
                p4 = fmaf(my_tanh(a), w4a, my_tanh(c) * w4b);
                p5 = fmaf(my_tanh(b), w4a, my_tanh(d) * w4b);
                up2(gj67, a, b); up2(gk67, c, d);
                p6 = fmaf(my_tanh(a), w4a, my_tanh(c) * w4b);
                p7 = fmaf(my_tanh(b), w4a, my_tanh(d) * w4b);
            }
#pragma unroll
            for (int off = 16; off > 0; off >>= 1) {
                p0 += __shfl_xor_sync(0xffffffffu, p0, off);
                p1 += __shfl_xor_sync(0xffffffffu, p1, off);
                p2 += __shfl_xor_sync(0xffffffffu, p2, off);
                p3 += __shfl_xor_sync(0xffffffffu, p3, off);
                p4 += __shfl_xor_sync(0xffffffffu, p4, off);
                p5 += __shfl_xor_sync(0xffffffffu, p5, off);
                p6 += __shfl_xor_sync(0xffffffffu, p6, off);
                p7 += __shfl_xor_sync(0xffffffffu, p7, off);
            }
            __syncwarp();   // z published; all h-loop reads of this step done

            // dh_pre = b2 + z @ W2^T (out k = lane), W2 row in registers.
            u64 d01 = PB2, d23 = PB2, d45 = PB2, d67 = PB2;
#pragma unroll
            for (int j = 0; j < HD_DIM; j++) {
                ulonglong2 zA = sZA[j], zB = sZB[j];
                u64 wd = pk2(w2r[j], w2r[j]);
                fma2(d01, zA.x, wd); fma2(d23, zA.y, wd);
                fma2(d45, zB.x, wd); fma2(d67, zB.y, wd);
            }

            // Euler updates.
            {
                float a, b;
                up2(d01, a, b); h0 = fmaf(cs[0], my_tanh(a), h0);
                                h1 = fmaf(cs[1], my_tanh(b), h1);
                up2(d23, a, b); h2 = fmaf(cs[2], my_tanh(a), h2);
                                h3 = fmaf(cs[3], my_tanh(b), h3);
                up2(d45, a, b); h4 = fmaf(cs[4], my_tanh(a), h4);
                                h5 = fmaf(cs[5], my_tanh(b), h5);
                up2(d67, a, b); h6 = fmaf(cs[6], my_tanh(a), h6);
                                h7 = fmaf(cs[7], my_tanh(b), h7);
            }
            y0 = fmaf(cs[0], p0 + b4v, y0);
            y1 = fmaf(cs[1], p1 + b4v, y1);
            y2 = fmaf(cs[2], p2 + b4v, y2);
            y3 = fmaf(cs[3], p3 + b4v, y3);
            y4 = fmaf(cs[4], p4 + b4v, y4);
            y5 = fmaf(cs[5], p5 + b4v, y5);
            y6 = fmaf(cs[6], p6 + b4v, y6);
            y7 = fmaf(cs[7], p7 + b4v, y7);

            sHA[lane] = make_ulonglong2(pk2(h0, h1), pk2(h2, h3));
            sHB[lane] = make_ulonglong2(pk2(h4, h5), pk2(h6, h7));
            __syncwarp();
        }

        // Output: lanes 0..7 write their element's y.
        {
            float yv = y0;
            if (lane == 1) yv = y1;
            if (lane == 2) yv = y2;
            if (lane == 3) yv = y3;
            if (lane == 4) yv = y4;
            if (lane == 5) yv = y5;
            if (lane == 6) yv = y6;
            if (lane == 7) yv = y7;
            if (lane < E) out[(e0 + lane) * T_STEPS + t] = yv;
        }
    }
}

extern "C" void kernel_launch(void* const* d_in, const int* in_sizes, int n_in,
                              void* d_out, int out_size) {
    (void)in_sizes; (void)n_in; (void)out_size;
    const float* dt = (const float*)d_in[0];
    const float* x  = (const float*)d_in[1];
    const float* W1 = (const float*)d_in[2];
    const float* b1 = (const float*)d_in[3];
    const float* W2 = (const float*)d_in[4];
    const float* b2 = (const float*)d_in[5];
    const float* W3 = (const float*)d_in[6];
    const float* b3 = (const float*)d_in[7];
    const float* W4 = (const float*)d_in[8];
    const float* b4 = (const float*)d_in[9];
    float* out = (float*)d_out;

    latentode2_kernel<<<GRID, 32>>>(
        dt, x, W1, b1, W2, b2, W3, b3, W4, b4, out);
}